// round 1
// baseline (speedup 1.0000x reference)
#include <cuda_runtime.h>
#include <math.h>

// Problem constants
#define T_    4096
#define H_    1024
#define F_    4096
#define E_    8
#define KTOP_ 2
#define S_    (T_ * KTOP_)

// GEMM tiling
#define BM  128
#define BN  128
#define BK  8
#define NTH 256

// ---------------------------------------------------------------------------
// Scratch (device globals; no runtime allocation allowed)
// ---------------------------------------------------------------------------
__device__ int   g_is64;          // 1 if selected_experts is int64, 0 if int32
__device__ int   g_cnt[E_];       // tokens-slots per expert
__device__ int   g_off[E_];       // exclusive prefix of g_cnt
__device__ int   g_fill[E_];      // scatter cursors
__device__ int   g_tok[S_];       // grouped slot -> token index
__device__ int   g_orig[S_];      // grouped slot -> original slot (t*K + k)
__device__ float g_cw[S_];        // grouped slot -> routing weight
__device__ float g_h[(size_t)S_ * F_];   // gelu(x W1 + b1), 128 MB
__device__ float g_y[(size_t)S_ * H_];   // cw*(h W2 + b2) per slot, 32 MB

__device__ __forceinline__ int sel_get(const void* sel, int i) {
    return g_is64 ? (int)((const long long*)sel)[i] : ((const int*)sel)[i];
}

// ---------------------------------------------------------------------------
// Packed f32x2 helpers (Blackwell FFMA2 path)
// ---------------------------------------------------------------------------
__device__ __forceinline__ unsigned long long pk2(float lo, float hi) {
    unsigned long long r;
    asm("mov.b64 %0, {%1, %2};" : "=l"(r) : "f"(lo), "f"(hi));
    return r;
}
__device__ __forceinline__ void upk2(unsigned long long v, float& lo, float& hi) {
    asm("mov.b64 {%0, %1}, %2;" : "=f"(lo), "=f"(hi) : "l"(v));
}
#define FMA2(d, a, b) asm("fma.rn.f32x2 %0, %1, %2, %0;" : "+l"(d) : "l"(a), "l"(b))

__device__ __forceinline__ float gelu_exact(float x) {
    return 0.5f * x * (1.0f + erff(x * 0.70710678118654752f));
}

// ---------------------------------------------------------------------------
// Routing
// ---------------------------------------------------------------------------
// Detect int32 vs int64 storage of selected_experts. If the buffer really is
// int64, every 8-byte word is a value in [0, E). If it is int32, pairs combine
// into (v0 | v1<<32) which is out of range unless every odd element is zero
// (probability ~ (1/E)^(S/2), i.e. never). Reads min(#int64 words) = S_/2,
// which is in bounds for both layouts.
__global__ void k_detect(const long long* sel64) {
    __shared__ int bad;
    if (threadIdx.x == 0) bad = 0;
    __syncthreads();
    for (int i = threadIdx.x; i < S_ / 2; i += blockDim.x) {
        long long v = sel64[i];
        if (v < 0 || v >= E_) bad = 1;
    }
    __syncthreads();
    if (threadIdx.x == 0) g_is64 = bad ? 0 : 1;
}

// Single-block histogram + prefix (E=8 is tiny).
__global__ void k_route1(const void* sel) {
    __shared__ int h[E_];
    int t = threadIdx.x;
    if (t < E_) h[t] = 0;
    __syncthreads();
    for (int i = t; i < S_; i += blockDim.x) {
        int e = sel_get(sel, i);
        if (e >= 0 && e < E_) atomicAdd(&h[e], 1);
    }
    __syncthreads();
    if (t == 0) {
        int a = 0;
        for (int e = 0; e < E_; e++) {
            g_off[e] = a; a += h[e];
            g_cnt[e] = h[e];
            g_fill[e] = 0;
        }
    }
}

__global__ void k_scatter(const void* sel, const float* __restrict__ ew) {
    int i = blockIdx.x * blockDim.x + threadIdx.x;
    if (i >= S_) return;
    int e = sel_get(sel, i);
    if (e >= 0 && e < E_) {
        int p = g_off[e] + atomicAdd(&g_fill[e], 1);
        g_tok[p]  = i / KTOP_;
        g_orig[p] = i;
        g_cw[p]   = ew[i];
    }
}

// ---------------------------------------------------------------------------
// Grouped GEMM. MODE 0: C = gelu(gather(hidden) @ W1[e] + b1[e]) -> g_h
//               MODE 1: C = cw * (g_h @ W2[e] + b2[e])           -> g_y[orig]
// blockIdx.y enumerates m-tiles packed per expert (worst-case bound S/BM + E).
// ---------------------------------------------------------------------------
template<int KDIM, int NDIM, int MODE>
__global__ void __launch_bounds__(NTH)
k_gemm(const float* __restrict__ X,
       const float* __restrict__ W,
       const float* __restrict__ bias)
{
    // Map linear m-tile -> (expert, row block)
    int mt = blockIdx.y;
    int e = -1, m0 = 0, ne = 0, accT = 0;
    #pragma unroll
    for (int i = 0; i < E_; i++) {
        int n  = g_cnt[i];
        int nt = (n + BM - 1) / BM;
        if (e < 0 && mt < accT + nt) { e = i; m0 = (mt - accT) * BM; ne = n; }
        accT += nt;
    }
    if (e < 0) return;

    const int n0  = blockIdx.x * BN;
    const int tid = threadIdx.x;
    const int off = g_off[e];

    __shared__ float As[2][BK][BM];
    __shared__ float Bs[2][BK][BN];

    // A tile loader: 128 rows x 8 cols; thread -> (row = tid/2, 4 cols)
    const int  a_row   = tid >> 1;
    const int  a_col   = (tid & 1) * 4;
    const bool a_valid = (m0 + a_row) < ne;
    const float* a_ptr = nullptr;
    if (a_valid) {
        int gi = off + m0 + a_row;
        const float* Asrc = (MODE == 0) ? X : (const float*)g_h;
        long long arow    = (MODE == 0) ? (long long)g_tok[gi] : (long long)gi;
        a_ptr = Asrc + arow * (long long)KDIM + a_col;
    }

    // B tile loader: 8 rows x 128 cols; thread -> (row = tid/32, 4 cols)
    const int b_row = tid >> 5;
    const int b_col = (tid & 31) * 4;
    const float* w_ptr = W + (size_t)e * KDIM * NDIM + (size_t)b_row * NDIM + n0 + b_col;

    // Micro-tile: 8x8 outputs per thread in 4 quads at (tr|tr+64, tc|tc+64)
    const int tr = (tid >> 4) * 4;
    const int tc = (tid & 15) * 4;

    unsigned long long acc[8][4];
    #pragma unroll
    for (int i = 0; i < 8; i++)
        #pragma unroll
        for (int p = 0; p < 4; p++) acc[i][p] = 0ULL;

    // Prologue: k-block 0 into buffer 0
    float4 a_reg = make_float4(0.f, 0.f, 0.f, 0.f);
    if (a_valid) a_reg = *(const float4*)a_ptr;
    float4 b_reg = *(const float4*)w_ptr;
    As[0][a_col + 0][a_row] = a_reg.x;
    As[0][a_col + 1][a_row] = a_reg.y;
    As[0][a_col + 2][a_row] = a_reg.z;
    As[0][a_col + 3][a_row] = a_reg.w;
    *(float4*)&Bs[0][b_row][b_col] = b_reg;
    __syncthreads();

    const int KB = KDIM / BK;
    for (int kb = 0; kb < KB; kb++) {
        const int buf = kb & 1;
        // Stage next k-block in registers (hide LDG under compute)
        if (kb + 1 < KB) {
            a_reg = make_float4(0.f, 0.f, 0.f, 0.f);
            if (a_valid) a_reg = *(const float4*)(a_ptr + (size_t)(kb + 1) * BK);
            b_reg = *(const float4*)(w_ptr + (size_t)(kb + 1) * BK * NDIM);
        }
        #pragma unroll
        for (int k = 0; k < BK; k++) {
            float4 a0  = *(const float4*)&As[buf][k][tr];
            float4 a1  = *(const float4*)&As[buf][k][tr + 64];
            float4 bv0 = *(const float4*)&Bs[buf][k][tc];
            float4 bv1 = *(const float4*)&Bs[buf][k][tc + 64];
            unsigned long long bp0 = pk2(bv0.x, bv0.y);
            unsigned long long bp1 = pk2(bv0.z, bv0.w);
            unsigned long long bp2 = pk2(bv1.x, bv1.y);
            unsigned long long bp3 = pk2(bv1.z, bv1.w);
            float av[8] = {a0.x, a0.y, a0.z, a0.w, a1.x, a1.y, a1.z, a1.w};
            #pragma unroll
            for (int i = 0; i < 8; i++) {
                unsigned long long ad = pk2(av[i], av[i]);
                FMA2(acc[i][0], ad, bp0);
                FMA2(acc[i][1], ad, bp1);
                FMA2(acc[i][2], ad, bp2);
                FMA2(acc[i][3], ad, bp3);
            }
        }
        if (kb + 1 < KB) {
            const int nb = buf ^ 1;
            As[nb][a_col + 0][a_row] = a_reg.x;
            As[nb][a_col + 1][a_row] = a_reg.y;
            As[nb][a_col + 2][a_row] = a_reg.z;
            As[nb][a_col + 3][a_row] = a_reg.w;
            *(float4*)&Bs[nb][b_row][b_col] = b_reg;
        }
        __syncthreads();
    }

    // Epilogue
    const float* bb = bias + (size_t)e * NDIM + n0;
    #pragma unroll
    for (int i = 0; i < 8; i++) {
        int row = (i < 4) ? (tr + i) : (tr + 60 + i);   // i>=4 -> tr+64+(i-4)
        int m = m0 + row;
        if (m >= ne) continue;
        int gi = off + m;
        if (MODE == 0) {
            float* dst = g_h + (size_t)gi * F_ + n0;
            #pragma unroll
            for (int p = 0; p < 4; p++) {
                int c = (p < 2) ? (tc + p * 2) : (tc + 60 + p * 2);
                float x, y; upk2(acc[i][p], x, y);
                x = gelu_exact(x + bb[c]);
                y = gelu_exact(y + bb[c + 1]);
                *(float2*)&dst[c] = make_float2(x, y);
            }
        } else {
            float cw = g_cw[gi];
            float* dst = g_y + (size_t)g_orig[gi] * H_ + n0;
            #pragma unroll
            for (int p = 0; p < 4; p++) {
                int c = (p < 2) ? (tc + p * 2) : (tc + 60 + p * 2);
                float x, y; upk2(acc[i][p], x, y);
                x = cw * (x + bb[c]);
                y = cw * (y + bb[c + 1]);
                *(float2*)&dst[c] = make_float2(x, y);
            }
        }
    }
}

// ---------------------------------------------------------------------------
// Final reduce over the K=2 slots of each token (deterministic, no atomics)
// ---------------------------------------------------------------------------
__global__ void k_reduce(const void* sel, float* __restrict__ out) {
    int idx = blockIdx.x * blockDim.x + threadIdx.x;
    if (idx >= T_ * H_) return;
    int t = idx / H_;
    int h = idx - t * H_;
    float s = 0.f;
    #pragma unroll
    for (int k = 0; k < KTOP_; k++) {
        int e = sel_get(sel, t * KTOP_ + k);
        if (e >= 0 && e < E_) s += g_y[(size_t)(t * KTOP_ + k) * H_ + h];
    }
    out[idx] = s;
}

// ---------------------------------------------------------------------------
// Launch
// ---------------------------------------------------------------------------
extern "C" void kernel_launch(void* const* d_in, const int* in_sizes, int n_in,
                              void* d_out, int out_size) {
    const float* hidden = (const float*)d_in[0];   // [T, H]
    const float* ew     = (const float*)d_in[1];   // [T, K]
    const float* W1     = (const float*)d_in[2];   // [E, H, F]
    const float* b1     = (const float*)d_in[3];   // [E, F]
    const float* W2     = (const float*)d_in[4];   // [E, F, H]
    const float* b2     = (const float*)d_in[5];   // [E, H]
    const void*  sel    = d_in[6];                 // [T, K] int32 or int64
    float* out = (float*)d_out;                    // [T, H]

    k_detect<<<1, 256>>>((const long long*)sel);
    k_route1<<<1, 1024>>>(sel);
    k_scatter<<<(S_ + 255) / 256, 256>>>(sel, ew);

    dim3 g1(F_ / BN, S_ / BM + E_);
    k_gemm<H_, F_, 0><<<g1, NTH>>>(hidden, W1, b1);

    dim3 g2(H_ / BN, S_ / BM + E_);
    k_gemm<F_, H_, 1><<<g2, NTH>>>(nullptr, W2, b2);

    k_reduce<<<(T_ * H_ + 255) / 256, 256>>>(sel, out);
}

// round 3
// speedup vs baseline: 1.6163x; 1.6163x over previous
#include <cuda_runtime.h>
#include <math.h>
#include <stdint.h>

// Problem constants
#define T_    4096
#define H_    1024
#define F_    4096
#define E_    8
#define KTOP_ 2
#define S_    (T_ * KTOP_)

// GEMM tiling
#define BM   128
#define BN   128
#define BK   32
#define NTH  256

// SMEM strides (floats), chosen for conflict-free fragment reads
#define AST  36    // 36 % 32 == 4  -> A-frag banks 4g+t, all distinct
#define BST  136   // 136 % 32 == 8 -> B-frag banks 8t+g, all distinct

#define ASZ  (BM * AST * 4)              // 18432 B per buffer
#define BSZ  (BK * BST * 4)              // 17408 B per buffer
#define SMEM_TOTAL (2 * ASZ + 2 * BSZ)   // 71680 B

// ---------------------------------------------------------------------------
// Scratch (device globals)
// ---------------------------------------------------------------------------
__device__ int   g_is64;
__device__ int   g_cnt[E_], g_off[E_], g_fill[E_];
__device__ int   g_tok[S_], g_orig[S_];
__device__ float g_cw[S_];
__device__ float g_h[(size_t)S_ * F_];   // 128 MB
__device__ float g_y[(size_t)S_ * H_];   // 32 MB

__device__ __forceinline__ int sel_get(const void* sel, int i) {
    return g_is64 ? (int)((const long long*)sel)[i] : ((const int*)sel)[i];
}
__device__ __forceinline__ float gelu_exact(float x) {
    return 0.5f * x * (1.0f + erff(x * 0.70710678118654752f));
}
__device__ __forceinline__ uint32_t to_tf32(float x) {
    uint32_t r;
    asm("cvt.rna.tf32.f32 %0, %1;" : "=r"(r) : "f"(x));
    return r;
}

// ---------------------------------------------------------------------------
// Routing (validated in R1)
// ---------------------------------------------------------------------------
__global__ void k_detect(const long long* sel64) {
    __shared__ int bad;
    if (threadIdx.x == 0) bad = 0;
    __syncthreads();
    for (int i = threadIdx.x; i < S_ / 2; i += blockDim.x) {
        long long v = sel64[i];
        if (v < 0 || v >= E_) bad = 1;
    }
    __syncthreads();
    if (threadIdx.x == 0) g_is64 = bad ? 0 : 1;
}

__global__ void k_route1(const void* sel) {
    __shared__ int h[E_];
    int t = threadIdx.x;
    if (t < E_) h[t] = 0;
    __syncthreads();
    for (int i = t; i < S_; i += blockDim.x) {
        int e = sel_get(sel, i);
        if (e >= 0 && e < E_) atomicAdd(&h[e], 1);
    }
    __syncthreads();
    if (t == 0) {
        int a = 0;
        for (int e = 0; e < E_; e++) { g_off[e] = a; a += h[e]; g_cnt[e] = h[e]; g_fill[e] = 0; }
    }
}

__global__ void k_scatter(const void* sel, const float* __restrict__ ew) {
    int i = blockIdx.x * blockDim.x + threadIdx.x;
    if (i >= S_) return;
    int e = sel_get(sel, i);
    if (e >= 0 && e < E_) {
        int p = g_off[e] + atomicAdd(&g_fill[e], 1);
        g_tok[p] = i / KTOP_; g_orig[p] = i; g_cw[p] = ew[i];
    }
}

// ---------------------------------------------------------------------------
// Grouped GEMM on mma.sync m16n8k8 tf32 (baseline PTX ISA; compiles sm_103).
// MODE 0: g_h = gelu(gather(hidden) @ W1[e] + b1[e])        W1: [K][N] row-major
// MODE 1: g_y[orig] = cw * (g_h @ W2[e] + b2[e])            W2: [K][N] row-major
// ---------------------------------------------------------------------------
#define MMA_TF32(c, a, b)                                                        \
    asm volatile("mma.sync.aligned.m16n8k8.row.col.f32.tf32.tf32.f32 "           \
        "{%0,%1,%2,%3}, {%4,%5,%6,%7}, {%8,%9}, {%0,%1,%2,%3};"                  \
        : "+f"((c)[0]), "+f"((c)[1]), "+f"((c)[2]), "+f"((c)[3])                  \
        : "r"((a)[0]), "r"((a)[1]), "r"((a)[2]), "r"((a)[3]),                     \
          "r"((b)[0]), "r"((b)[1]))

template<int KDIM, int NDIM, int MODE>
__global__ void __launch_bounds__(NTH)
k_mma(const float* __restrict__ X, const float* __restrict__ W,
      const float* __restrict__ bias)
{
    // m-tile -> (expert, row block)
    int mt = blockIdx.y;
    int e = -1, m0 = 0, ne = 0, acc = 0;
    #pragma unroll
    for (int i = 0; i < E_; i++) {
        int n = g_cnt[i]; int nt = (n + BM - 1) / BM;
        if (e < 0 && mt < acc + nt) { e = i; m0 = (mt - acc) * BM; ne = n; }
        acc += nt;
    }
    if (e < 0) return;

    const int n0  = blockIdx.x * BN;
    const int tid = threadIdx.x;
    const int off = g_off[e];

    extern __shared__ char smem[];
    float* As[2] = { (float*)smem,               (float*)(smem + ASZ) };
    float* Bs[2] = { (float*)(smem + 2 * ASZ),   (float*)(smem + 2 * ASZ + BSZ) };

    // ---- staging geometry -------------------------------------------------
    // A: 4 passes; pass i: row = (tid>>3) + 32*i, col quad = (tid&7)*4
    // B: 4 passes; pass i: krow = (tid>>5) + 8*i, col quad = (tid&31)*4
    const int a_kq = (tid & 7) * 4;
    const int b_nq = (tid & 31) * 4;
    const float* aptr[4]; bool avld[4]; int a_soff[4];
    #pragma unroll
    for (int i = 0; i < 4; i++) {
        int r = (tid >> 3) + 32 * i;
        int m = m0 + r;
        avld[i] = (m < ne);
        int gi = off + (avld[i] ? m : 0);
        const float* src = (MODE == 0) ? X + (size_t)g_tok[gi] * KDIM
                                       : g_h + (size_t)gi * KDIM;
        aptr[i]   = src + a_kq;
        a_soff[i] = r * AST + a_kq;
    }
    const float* We = W + (size_t)e * KDIM * NDIM;
    const float* bptr[4]; int b_soff[4];
    #pragma unroll
    for (int i = 0; i < 4; i++) {
        int kr = (tid >> 5) + 8 * i;
        bptr[i]   = We + (size_t)kr * NDIM + n0 + b_nq;
        b_soff[i] = kr * BST + b_nq;
    }

    // ---- fragment geometry --------------------------------------------------
    const int lane = tid & 31, wid = tid >> 5;
    const int warp_m = (wid >> 1) * 32;   // 4 warps down
    const int warp_n = (wid & 1) * 64;    // 2 warps across
    const int fg = lane >> 2;             // groupID
    const int ft = lane & 3;              // threadID_in_group

    float c[2][8][4];
    #pragma unroll
    for (int mf = 0; mf < 2; mf++)
        #pragma unroll
        for (int nf = 0; nf < 8; nf++)
            #pragma unroll
            for (int r = 0; r < 4; r++) c[mf][nf][r] = 0.f;

    // ---- prologue: stage chunk 0 into buffer 0 ----
    float4 ar[4], br[4];
    #pragma unroll
    for (int i = 0; i < 4; i++) {
        ar[i] = avld[i] ? *(const float4*)aptr[i] : make_float4(0.f, 0.f, 0.f, 0.f);
        br[i] = *(const float4*)bptr[i];
    }
    #pragma unroll
    for (int i = 0; i < 4; i++) {
        uint4 a4 = make_uint4(to_tf32(ar[i].x), to_tf32(ar[i].y), to_tf32(ar[i].z), to_tf32(ar[i].w));
        uint4 b4 = make_uint4(to_tf32(br[i].x), to_tf32(br[i].y), to_tf32(br[i].z), to_tf32(br[i].w));
        *(uint4*)(As[0] + a_soff[i]) = a4;
        *(uint4*)(Bs[0] + b_soff[i]) = b4;
    }
    __syncthreads();

    const int KB = KDIM / BK;
    for (int kb = 0; kb < KB; kb++) {
        const int buf = kb & 1;
        if (kb + 1 < KB) {       // prefetch next chunk to registers
            #pragma unroll
            for (int i = 0; i < 4; i++) {
                ar[i] = avld[i] ? *(const float4*)(aptr[i] + (size_t)(kb + 1) * BK)
                                : make_float4(0.f, 0.f, 0.f, 0.f);
                br[i] = *(const float4*)(bptr[i] + (size_t)(kb + 1) * BK * NDIM);
            }
        }
        // ---- compute on buf ----
        const uint32_t* Au = (const uint32_t*)As[buf];
        const uint32_t* Bu = (const uint32_t*)Bs[buf];
        #pragma unroll
        for (int ks = 0; ks < 4; ks++) {
            uint32_t a[2][4];
            #pragma unroll
            for (int mf = 0; mf < 2; mf++) {
                int rb = warp_m + mf * 16 + fg;
                int cb = ks * 8 + ft;
                a[mf][0] = Au[rb * AST + cb];
                a[mf][1] = Au[(rb + 8) * AST + cb];
                a[mf][2] = Au[rb * AST + cb + 4];
                a[mf][3] = Au[(rb + 8) * AST + cb + 4];
            }
            uint32_t b[8][2];
            #pragma unroll
            for (int nf = 0; nf < 8; nf++) {
                int col = warp_n + nf * 8 + fg;
                b[nf][0] = Bu[(ks * 8 + ft) * BST + col];
                b[nf][1] = Bu[(ks * 8 + ft + 4) * BST + col];
            }
            #pragma unroll
            for (int mf = 0; mf < 2; mf++)
                #pragma unroll
                for (int nf = 0; nf < 8; nf++)
                    MMA_TF32(c[mf][nf], a[mf], b[nf]);
        }
        // ---- store prefetched chunk into other buffer ----
        if (kb + 1 < KB) {
            const int nb = buf ^ 1;
            #pragma unroll
            for (int i = 0; i < 4; i++) {
                uint4 a4 = make_uint4(to_tf32(ar[i].x), to_tf32(ar[i].y), to_tf32(ar[i].z), to_tf32(ar[i].w));
                uint4 b4 = make_uint4(to_tf32(br[i].x), to_tf32(br[i].y), to_tf32(br[i].z), to_tf32(br[i].w));
                *(uint4*)(As[nb] + a_soff[i]) = a4;
                *(uint4*)(Bs[nb] + b_soff[i]) = b4;
            }
        }
        __syncthreads();
    }

    // ---- epilogue ----
    const float* bb = bias + (size_t)e * NDIM + n0;
    #pragma unroll
    for (int mf = 0; mf < 2; mf++) {
        #pragma unroll
        for (int half = 0; half < 2; half++) {       // c0/c1 (row fg) vs c2/c3 (row fg+8)
            int r = warp_m + mf * 16 + fg + half * 8;
            int m = m0 + r;
            if (m >= ne) continue;
            int gi = off + m;
            float cw = (MODE == 1) ? g_cw[gi] : 0.f;
            float* drow = (MODE == 0) ? g_h + (size_t)gi * F_ + n0
                                      : g_y + (size_t)g_orig[gi] * H_ + n0;
            #pragma unroll
            for (int nf = 0; nf < 8; nf++) {
                int col = warp_n + nf * 8 + 2 * ft;
                float2 bv = *(const float2*)(bb + col);
                float v0 = c[mf][nf][half * 2 + 0] + bv.x;
                float v1 = c[mf][nf][half * 2 + 1] + bv.y;
                float2 o;
                if (MODE == 0) { o.x = gelu_exact(v0); o.y = gelu_exact(v1); }
                else           { o.x = cw * v0;        o.y = cw * v1; }
                *(float2*)(drow + col) = o;
            }
        }
    }
}

// ---------------------------------------------------------------------------
// Final reduce over the K=2 slots of each token
// ---------------------------------------------------------------------------
__global__ void k_reduce(const void* sel, float* __restrict__ out) {
    int i4 = blockIdx.x * blockDim.x + threadIdx.x;
    if (i4 >= T_ * H_ / 4) return;
    int t = i4 / (H_ / 4);
    int c = i4 % (H_ / 4);
    float4 s = make_float4(0.f, 0.f, 0.f, 0.f);
    #pragma unroll
    for (int k = 0; k < KTOP_; k++) {
        int e = sel_get(sel, t * KTOP_ + k);
        if (e >= 0 && e < E_) {
            float4 v = ((const float4*)g_y)[(size_t)(t * KTOP_ + k) * (H_ / 4) + c];
            s.x += v.x; s.y += v.y; s.z += v.z; s.w += v.w;
        }
    }
    ((float4*)out)[i4] = s;
}

// ---------------------------------------------------------------------------
// Launch
// ---------------------------------------------------------------------------
extern "C" void kernel_launch(void* const* d_in, const int* in_sizes, int n_in,
                              void* d_out, int out_size) {
    const float* hidden = (const float*)d_in[0];
    const float* ew     = (const float*)d_in[1];
    const float* W1     = (const float*)d_in[2];
    const float* b1     = (const float*)d_in[3];
    const float* W2     = (const float*)d_in[4];
    const float* b2     = (const float*)d_in[5];
    const void*  sel    = d_in[6];
    float* out = (float*)d_out;

    cudaFuncSetAttribute(k_mma<H_, F_, 0>, cudaFuncAttributeMaxDynamicSharedMemorySize, SMEM_TOTAL);
    cudaFuncSetAttribute(k_mma<F_, H_, 1>, cudaFuncAttributeMaxDynamicSharedMemorySize, SMEM_TOTAL);

    k_detect<<<1, 256>>>((const long long*)sel);
    k_route1<<<1, 1024>>>(sel);
    k_scatter<<<(S_ + 255) / 256, 256>>>(sel, ew);

    const int MT = S_ / BM + E_;  // 72 worst-case m-tiles
    k_mma<H_, F_, 0><<<dim3(F_ / BN, MT), NTH, SMEM_TOTAL>>>(hidden, W1, b1);
    k_mma<F_, H_, 1><<<dim3(H_ / BN, MT), NTH, SMEM_TOTAL>>>(hidden, W2, b2);

    k_reduce<<<(T_ * H_ / 4 + 255) / 256, 256>>>(sel, out);
}

// round 4
// speedup vs baseline: 2.9308x; 1.8133x over previous
#include <cuda_runtime.h>
#include <math.h>
#include <stdint.h>

// Problem constants
#define T_    4096
#define H_    1024
#define F_    4096
#define E_    8
#define KTOP_ 2
#define S_    (T_ * KTOP_)

// GEMM tiling
#define BM     128
#define BN     128
#define BK     32
#define NTH    256
#define STAGES 3

// SMEM strides (floats), conflict-free fragment reads
#define AST  36    // 36 % 32 == 4
#define BST  136   // 136 % 32 == 8

#define ASZ  (BM * AST * 4)       // 18432 B
#define BSZ  (BK * BST * 4)       // 17408 B
#define STG  (ASZ + BSZ)          // 35840 B per stage
#define SMEM_TOTAL (STAGES * STG) // 107520 B

// ---------------------------------------------------------------------------
// Scratch (device globals)
// ---------------------------------------------------------------------------
__device__ int   g_is64;
__device__ int   g_cnt[E_], g_off[E_], g_fill[E_];
__device__ int   g_tok[S_], g_orig[S_];
__device__ float g_cw[S_];
__device__ float g_h[(size_t)S_ * F_];          // 128 MB (tf32-rounded)
__device__ float g_y[(size_t)S_ * H_];          // 32 MB
__device__ float g_xr[(size_t)T_ * H_];         // 16 MB  hidden, tf32-rounded
__device__ float g_w1r[(size_t)E_ * H_ * F_];   // 134 MB W1, tf32-rounded
__device__ float g_w2r[(size_t)E_ * F_ * H_];   // 134 MB W2, tf32-rounded

__device__ __forceinline__ int sel_get(const void* sel, int i) {
    return g_is64 ? (int)((const long long*)sel)[i] : ((const int*)sel)[i];
}
__device__ __forceinline__ float gelu_exact(float x) {
    return 0.5f * x * (1.0f + erff(x * 0.70710678118654752f));
}
__device__ __forceinline__ uint32_t to_tf32(float x) {
    uint32_t r;
    asm("cvt.rna.tf32.f32 %0, %1;" : "=r"(r) : "f"(x));
    return r;
}
__device__ __forceinline__ uint32_t smem_u32(const void* p) {
    uint32_t a;
    asm("{ .reg .u64 t; cvta.to.shared.u64 t, %1; cvt.u32.u64 %0, t; }" : "=r"(a) : "l"(p));
    return a;
}

// cp.async 16B with runtime src-size (0 => zero-fill)
__device__ __forceinline__ void cp16(uint32_t dst, const void* src, uint32_t nbytes) {
    asm volatile("cp.async.cg.shared.global [%0], [%1], 16, %2;"
                 :: "r"(dst), "l"(src), "r"(nbytes) : "memory");
}
#define CP_COMMIT() asm volatile("cp.async.commit_group;" ::: "memory")
#define CP_WAIT(n)  asm volatile("cp.async.wait_group %0;" :: "n"(n) : "memory")

// ---------------------------------------------------------------------------
// Routing (validated)
// ---------------------------------------------------------------------------
__global__ void k_detect(const long long* sel64) {
    __shared__ int bad;
    if (threadIdx.x == 0) bad = 0;
    __syncthreads();
    for (int i = threadIdx.x; i < S_ / 2; i += blockDim.x) {
        long long v = sel64[i];
        if (v < 0 || v >= E_) bad = 1;
    }
    __syncthreads();
    if (threadIdx.x == 0) g_is64 = bad ? 0 : 1;
}

__global__ void k_route1(const void* sel) {
    __shared__ int h[E_];
    int t = threadIdx.x;
    if (t < E_) h[t] = 0;
    __syncthreads();
    for (int i = t; i < S_; i += blockDim.x) {
        int e = sel_get(sel, i);
        if (e >= 0 && e < E_) atomicAdd(&h[e], 1);
    }
    __syncthreads();
    if (t == 0) {
        int a = 0;
        for (int e = 0; e < E_; e++) { g_off[e] = a; a += h[e]; g_cnt[e] = h[e]; g_fill[e] = 0; }
    }
}

__global__ void k_scatter(const void* sel, const float* __restrict__ ew) {
    int i = blockIdx.x * blockDim.x + threadIdx.x;
    if (i >= S_) return;
    int e = sel_get(sel, i);
    if (e >= 0 && e < E_) {
        int p = g_off[e] + atomicAdd(&g_fill[e], 1);
        g_tok[p] = i / KTOP_; g_orig[p] = i; g_cw[p] = ew[i];
    }
}

// ---------------------------------------------------------------------------
// tf32 pre-round pass (float4 copy with cvt.rna)
// ---------------------------------------------------------------------------
__global__ void k_round(const float4* __restrict__ src, float4* __restrict__ dst, int n4) {
    int i = blockIdx.x * blockDim.x + threadIdx.x;
    if (i >= n4) return;
    float4 v = src[i];
    uint4 r = make_uint4(to_tf32(v.x), to_tf32(v.y), to_tf32(v.z), to_tf32(v.w));
    dst[i] = *(float4*)&r;
}

// ---------------------------------------------------------------------------
// Grouped GEMM, mma.sync m16n8k8 tf32, cp.async 3-stage pipeline.
// Inputs are pre-rounded to tf32 bit patterns (raw 16B copies in staging).
// MODE 0: g_h = tf32(gelu(gather(g_xr) @ g_w1r[e] + b1[e]))
// MODE 1: g_y[orig] = cw * (g_h @ g_w2r[e] + b2[e])
// ---------------------------------------------------------------------------
#define MMA_TF32(c, a, b)                                                        \
    asm volatile("mma.sync.aligned.m16n8k8.row.col.f32.tf32.tf32.f32 "           \
        "{%0,%1,%2,%3}, {%4,%5,%6,%7}, {%8,%9}, {%0,%1,%2,%3};"                  \
        : "+f"((c)[0]), "+f"((c)[1]), "+f"((c)[2]), "+f"((c)[3])                  \
        : "r"((a)[0]), "r"((a)[1]), "r"((a)[2]), "r"((a)[3]),                     \
          "r"((b)[0]), "r"((b)[1]))

template<int KDIM, int NDIM, int MODE>
__global__ void __launch_bounds__(NTH, 2)
k_mma(const float* __restrict__ X, const float* __restrict__ W,
      const float* __restrict__ bias)
{
    // m-tile -> (expert, row block)
    int mt = blockIdx.y;
    int e = -1, m0 = 0, ne = 0, acc = 0;
    #pragma unroll
    for (int i = 0; i < E_; i++) {
        int n = g_cnt[i]; int nt = (n + BM - 1) / BM;
        if (e < 0 && mt < acc + nt) { e = i; m0 = (mt - acc) * BM; ne = n; }
        acc += nt;
    }
    if (e < 0) return;

    const int n0  = blockIdx.x * BN;
    const int tid = threadIdx.x;
    const int off = g_off[e];

    extern __shared__ char smem[];
    const uint32_t sbase = smem_u32(smem);

    // ---- staging geometry (per-thread 4 A rows + 4 B rows, 16B each) ----
    const int a_kq = (tid & 7) * 4;          // k quad within chunk
    const int b_nq = (tid & 31) * 4;         // n quad
    const float* aptr[4]; uint32_t abytes[4]; uint32_t a_soff[4];
    #pragma unroll
    for (int i = 0; i < 4; i++) {
        int r = (tid >> 3) + 32 * i;
        int m = m0 + r;
        bool v = (m < ne);
        int gi = off + (v ? m : 0);
        const float* src = (MODE == 0) ? X + (size_t)g_tok[gi] * KDIM
                                       : g_h + (size_t)gi * KDIM;
        aptr[i]   = src + a_kq;
        abytes[i] = v ? 16u : 0u;
        a_soff[i] = (uint32_t)(r * AST + a_kq) * 4u;
    }
    const float* We = W + (size_t)e * KDIM * NDIM;
    const float* bptr[4]; uint32_t b_soff[4];
    #pragma unroll
    for (int i = 0; i < 4; i++) {
        int kr = (tid >> 5) + 8 * i;
        bptr[i]   = We + (size_t)kr * NDIM + n0 + b_nq;
        b_soff[i] = (uint32_t)(kr * BST + b_nq) * 4u;
    }

    constexpr int KB = KDIM / BK;

    auto issue = [&](int stage, int kb) {
        uint32_t Ab = sbase + stage * STG;
        uint32_t Bb = Ab + ASZ;
        const int k0 = kb * BK;
        #pragma unroll
        for (int i = 0; i < 4; i++) cp16(Ab + a_soff[i], aptr[i] + k0, abytes[i]);
        #pragma unroll
        for (int i = 0; i < 4; i++) cp16(Bb + b_soff[i], bptr[i] + (size_t)k0 * NDIM, 16u);
    };

    // ---- fragment geometry ----
    const int lane = tid & 31, wid = tid >> 5;
    const int warp_m = (wid >> 1) * 32;
    const int warp_n = (wid & 1) * 64;
    const int fg = lane >> 2;
    const int ft = lane & 3;

    float c[2][8][4];
    #pragma unroll
    for (int mf = 0; mf < 2; mf++)
        #pragma unroll
        for (int nf = 0; nf < 8; nf++)
            #pragma unroll
            for (int r = 0; r < 4; r++) c[mf][nf][r] = 0.f;

    // ---- prologue: stages 0..STAGES-2 ----
    #pragma unroll
    for (int s = 0; s < STAGES - 1; s++) { issue(s, s); CP_COMMIT(); }

    for (int kb = 0; kb < KB; kb++) {
        CP_WAIT(STAGES - 2);          // chunk kb landed
        __syncthreads();              // visible to all; prev compute done

        // refill the buffer freed last iteration
        if (kb + STAGES - 1 < KB) issue((kb + STAGES - 1) % STAGES, kb + STAGES - 1);
        CP_COMMIT();

        const int buf = kb % STAGES;
        const uint32_t* Au = (const uint32_t*)(smem + buf * STG);
        const uint32_t* Bu = (const uint32_t*)(smem + buf * STG + ASZ);
        #pragma unroll
        for (int ks = 0; ks < 4; ks++) {
            uint32_t a[2][4];
            #pragma unroll
            for (int mf = 0; mf < 2; mf++) {
                int rb = warp_m + mf * 16 + fg;
                int cb = ks * 8 + ft;
                a[mf][0] = Au[rb * AST + cb];
                a[mf][1] = Au[(rb + 8) * AST + cb];
                a[mf][2] = Au[rb * AST + cb + 4];
                a[mf][3] = Au[(rb + 8) * AST + cb + 4];
            }
            uint32_t b[8][2];
            #pragma unroll
            for (int nf = 0; nf < 8; nf++) {
                int col = warp_n + nf * 8 + fg;
                b[nf][0] = Bu[(ks * 8 + ft) * BST + col];
                b[nf][1] = Bu[(ks * 8 + ft + 4) * BST + col];
            }
            #pragma unroll
            for (int mf = 0; mf < 2; mf++)
                #pragma unroll
                for (int nf = 0; nf < 8; nf++)
                    MMA_TF32(c[mf][nf], a[mf], b[nf]);
        }
        __syncthreads();              // protect buf from refill next iter
    }

    // ---- epilogue ----
    const float* bb = bias + (size_t)e * NDIM + n0;
    #pragma unroll
    for (int mf = 0; mf < 2; mf++) {
        #pragma unroll
        for (int half = 0; half < 2; half++) {
            int r = warp_m + mf * 16 + fg + half * 8;
            int m = m0 + r;
            if (m >= ne) continue;
            int gi = off + m;
            float cw = (MODE == 1) ? g_cw[gi] : 0.f;
            float* drow = (MODE == 0) ? g_h + (size_t)gi * F_ + n0
                                      : g_y + (size_t)g_orig[gi] * H_ + n0;
            #pragma unroll
            for (int nf = 0; nf < 8; nf++) {
                int col = warp_n + nf * 8 + 2 * ft;
                float2 bv = *(const float2*)(bb + col);
                float v0 = c[mf][nf][half * 2 + 0] + bv.x;
                float v1 = c[mf][nf][half * 2 + 1] + bv.y;
                float2 o;
                if (MODE == 0) {
                    // round activations so GEMM2 staging can copy raw bytes
                    uint32_t u0 = to_tf32(gelu_exact(v0));
                    uint32_t u1 = to_tf32(gelu_exact(v1));
                    o.x = __uint_as_float(u0); o.y = __uint_as_float(u1);
                } else {
                    o.x = cw * v0; o.y = cw * v1;
                }
                *(float2*)(drow + col) = o;
            }
        }
    }
}

// ---------------------------------------------------------------------------
// Final reduce over the K=2 slots of each token
// ---------------------------------------------------------------------------
__global__ void k_reduce(const void* sel, float* __restrict__ out) {
    int i4 = blockIdx.x * blockDim.x + threadIdx.x;
    if (i4 >= T_ * H_ / 4) return;
    int t = i4 / (H_ / 4);
    int c = i4 % (H_ / 4);
    float4 s = make_float4(0.f, 0.f, 0.f, 0.f);
    #pragma unroll
    for (int k = 0; k < KTOP_; k++) {
        int e = sel_get(sel, t * KTOP_ + k);
        if (e >= 0 && e < E_) {
            float4 v = ((const float4*)g_y)[(size_t)(t * KTOP_ + k) * (H_ / 4) + c];
            s.x += v.x; s.y += v.y; s.z += v.z; s.w += v.w;
        }
    }
    ((float4*)out)[i4] = s;
}

// ---------------------------------------------------------------------------
// Launch
// ---------------------------------------------------------------------------
extern "C" void kernel_launch(void* const* d_in, const int* in_sizes, int n_in,
                              void* d_out, int out_size) {
    const float* hidden = (const float*)d_in[0];
    const float* ew     = (const float*)d_in[1];
    const float* W1     = (const float*)d_in[2];
    const float* b1     = (const float*)d_in[3];
    const float* W2     = (const float*)d_in[4];
    const float* b2     = (const float*)d_in[5];
    const void*  sel    = d_in[6];
    float* out = (float*)d_out;

    cudaFuncSetAttribute(k_mma<H_, F_, 0>, cudaFuncAttributeMaxDynamicSharedMemorySize, SMEM_TOTAL);
    cudaFuncSetAttribute(k_mma<F_, H_, 1>, cudaFuncAttributeMaxDynamicSharedMemorySize, SMEM_TOTAL);

    float* xr;  cudaGetSymbolAddress((void**)&xr,  g_xr);
    float* w1r; cudaGetSymbolAddress((void**)&w1r, g_w1r);
    float* w2r; cudaGetSymbolAddress((void**)&w2r, g_w2r);

    k_detect<<<1, 256>>>((const long long*)sel);
    k_route1<<<1, 1024>>>(sel);
    k_scatter<<<(S_ + 255) / 256, 256>>>(sel, ew);

    // tf32 pre-round: hidden, W1, W2
    {
        int n4;
        n4 = T_ * H_ / 4;
        k_round<<<(n4 + 255) / 256, 256>>>((const float4*)hidden, (float4*)xr, n4);
        n4 = E_ * H_ * F_ / 4;
        k_round<<<(n4 + 255) / 256, 256>>>((const float4*)W1, (float4*)w1r, n4);
        n4 = E_ * F_ * H_ / 4;
        k_round<<<(n4 + 255) / 256, 256>>>((const float4*)W2, (float4*)w2r, n4);
    }

    const int MT = S_ / BM + E_;  // 72 worst-case m-tiles
    k_mma<H_, F_, 0><<<dim3(F_ / BN, MT), NTH, SMEM_TOTAL>>>(xr, w1r, b1);
    k_mma<F_, H_, 1><<<dim3(H_ / BN, MT), NTH, SMEM_TOTAL>>>(nullptr, w2r, b2);

    k_reduce<<<(T_ * H_ / 4 + 255) / 256, 256>>>(sel, out);
}